// round 12
// baseline (speedup 1.0000x reference)
#include <cuda_runtime.h>
#include <cuda_bf16.h>
#include <cstdint>

#define BB 256
#define TT 512
#define NS 256
#define START_TAG 254
#define STOP_TAG 255
#define LN2F 0.6931471805599453f
#define NB 8
#define NCTA_G (2 * BB / NB)   // 64 CTAs, 32 clusters of 2
#define RSB 528                // ea row stride bytes (132 words -> conflict-free)
#define EABUF (NB * RSB)       // 4224

// scratch (allocation-free rule: __device__ globals)
__device__ float g_den[BB];
__device__ float g_num[BB];
// E = exp(trans) bf16, columns PRE-PERMUTED: g_Ebf[r*256+x] = exp(trans[r][perm(x)])
// perm(x) = 128*(x>>7) + 16*((x>>4)&7) + ((x>>1)&7) + 8*(x&1)
__device__ unsigned short g_Ebf[NS * NS];

__device__ __forceinline__ int permf(int x) {
    return 128 * (x >> 7) + 16 * ((x >> 4) & 7) + ((x >> 1) & 7) + 8 * (x & 1);
}
// inverse: s = 128A + 16w + g + 8h  ->  x = 128A + 2*(8w+g) + h
__device__ __forceinline__ int iperm(int s) {
    return 128 * (s >> 7) + 2 * (8 * ((s >> 4) & 7) + (s & 7)) + ((s >> 3) & 1);
}

// ---------------------------------------------------------------------------
// smem layout (static)
// ---------------------------------------------------------------------------
#define SM_EA    0        // 2 x 4224 ea double buffer: [n][x] bf16 (permuted states)
#define SM_MASK  8512     // 512 u32 mask bitfields
#define SM_C0    10560    // 8 floats
#define SM_RED   10592    // 64 floats
#define SM_KS    10848    // 8 ints
#define SM_SS    10880    // 8 floats
#define SM_BAR   10912    // 2 mbarriers (16B)
#define SM_TOTAL 10928

#define MMA_BF16(d, a, b0, b1) \
    asm volatile( \
        "mma.sync.aligned.m16n8k16.row.col.f32.bf16.bf16.f32 " \
        "{%0,%1,%2,%3},{%4,%5,%6,%7},{%8,%9},{%0,%1,%2,%3};" \
        : "+f"((d)[0]), "+f"((d)[1]), "+f"((d)[2]), "+f"((d)[3]) \
        : "r"((a)[0]), "r"((a)[1]), "r"((a)[2]), "r"((a)[3]), "r"(b0), "r"(b1))

#define MBAR_INIT(ad, n) \
    asm volatile("mbarrier.init.shared.b64 [%0], %1;" :: "r"(ad), "r"(n) : "memory")

// spin-wait with cluster-scope acquire
#define MBAR_WAIT_CL(ad, par) \
    asm volatile( \
        "{\n\t.reg .pred P;\n\t" \
        "WL_%=:\n\t" \
        "mbarrier.try_wait.parity.acquire.cluster.shared::cta.b64 P, [%0], %1, 0x989680;\n\t" \
        "@!P bra WL_%=;\n\t}" \
        :: "r"(ad), "r"(par) : "memory")

#define CLUSTER_SYNC() do { \
    asm volatile("barrier.cluster.arrive.aligned;" ::: "memory"); \
    asm volatile("barrier.cluster.wait.aligned;" ::: "memory"); \
} while (0)

__device__ __forceinline__ void st_remote_b32(uint32_t local_ad, uint32_t peer, uint32_t v) {
    asm volatile(
        "{\n\t.reg .b32 ra;\n\t"
        "mapa.shared::cluster.u32 ra, %0, %1;\n\t"
        "st.shared::cluster.b32 [ra], %2;\n\t}"
        :: "r"(local_ad), "r"(peer), "r"(v) : "memory");
}
__device__ __forceinline__ void mbar_arrive_remote(uint32_t local_ad, uint32_t peer) {
    asm volatile(
        "{\n\t.reg .b32 ra;\n\t"
        "mapa.shared::cluster.u32 ra, %0, %1;\n\t"
        "mbarrier.arrive.shared::cluster.b64 _, [ra];\n\t}"
        :: "r"(local_ad), "r"(peer) : "memory");
}

// ---------------------------------------------------------------------------
// Prep: permuted bf16 E
// ---------------------------------------------------------------------------
__global__ void prep_kernel(const float* __restrict__ trans) {
    int gid = blockIdx.x * blockDim.x + threadIdx.x;  // 0..65535
    int r = gid >> 8, x = gid & 255;
    g_Ebf[gid] = __bfloat16_as_ushort(__float2bfloat16(__expf(trans[r * NS + permf(x)])));
}

// ---------------------------------------------------------------------------
// Forward recursion: 2-CTA cluster; rank owns 128 states, full K=256.
// Own-half MMA overlaps the DSMEM arrival of the peer ea half.
// ---------------------------------------------------------------------------
__global__ void __launch_bounds__(256, 1) __cluster_dims__(2, 1, 1)
forward_kernel(const float* __restrict__ inputs,
               const float* __restrict__ trans,
               const int* __restrict__ mask)
{
    __shared__ __align__(16) char smem[SM_TOTAL];
    const uint32_t smem_base = (uint32_t)__cvta_generic_to_shared(smem);
    uint32_t* masksS = (uint32_t*)(smem + SM_MASK);
    float*    C0sm   = (float*)(smem + SM_C0);
    float*    redsm  = (float*)(smem + SM_RED);
    int*      kssm   = (int*)(smem + SM_KS);
    float*    Ssm    = (float*)(smem + SM_SS);

    const int tid  = threadIdx.x;
    const int lane = tid & 31;
    const int wid  = tid >> 5;
    const int gidr = lane >> 2;
    const int tig  = lane & 3;
    uint32_t rank;
    asm("mov.u32 %0, %%cluster_ctarank;" : "=r"(rank));
    const uint32_t peer = rank ^ 1u;
    const int bb = (blockIdx.x >> 1) * NB;
    const int n0 = 2 * tig, n1 = n0 + 1;
    const uint32_t bar0 = smem_base + SM_BAR;
    const uint32_t bar1 = smem_base + SM_BAR + 8;

    // mask bitfields
    for (int tt = tid; tt < TT; tt += 256) {
        uint32_t w = 0;
#pragma unroll
        for (int n = 0; n < NB; n++) w |= (mask[(bb + n) * TT + tt] ? 1u : 0u) << n;
        masksS[tt] = w;
    }

    // A fragments: this warp's m16 tile = own states 128*rank + 16*wid + {gidr, gidr+8}
    const int r0s = 128 * (int)rank + 16 * wid + gidr;
    const int r1s = r0s + 8;
    uint32_t A[16][4];
#pragma unroll
    for (int kt = 0; kt < 16; kt++) {
        int c0 = kt * 16 + tig * 2;
        A[kt][0] = *(const uint32_t*)&g_Ebf[r0s * NS + c0];
        A[kt][1] = *(const uint32_t*)&g_Ebf[r1s * NS + c0];
        A[kt][2] = *(const uint32_t*)&g_Ebf[r0s * NS + c0 + 8];
        A[kt][3] = *(const uint32_t*)&g_Ebf[r1s * NS + c0 + 8];
    }

    // init: both CTAs compute FULL 256-state ea0 locally (redundant, consistent)
    {
        float a0v[NB];
        float tS = trans[tid * NS + START_TAG];
#pragma unroll
        for (int n = 0; n < NB; n++)
            a0v[n] = tS + inputs[((size_t)(bb + n) * TT) * NS + tid];
#pragma unroll
        for (int n = 0; n < NB; n++) {
            float m = a0v[n];
#pragma unroll
            for (int o = 16; o; o >>= 1) m = fmaxf(m, __shfl_xor_sync(~0u, m, o));
            if (lane == 0) redsm[wid * 8 + n] = m;
        }
        __syncthreads();
        if (tid < 8) {
            float m = -INFINITY;
#pragma unroll
            for (int w = 0; w < 8; w++) m = fmaxf(m, redsm[w * 8 + tid]);
            C0sm[tid] = m;
        }
        __syncthreads();
        int xph = iperm(tid);
#pragma unroll
        for (int n = 0; n < NB; n++) {
            float e = __expf(a0v[n] - C0sm[n]);
            unsigned short h = __bfloat16_as_ushort(__float2bfloat16(e));
            uint32_t ad = smem_base + SM_EA + (uint32_t)(n * RSB + xph * 2);
            asm volatile("st.shared.b16 [%0], %1;" :: "r"(ad), "h"(h));
        }
        if (tid == 0) { MBAR_INIT(bar0, 1); MBAR_INIT(bar1, 1); }
        __syncthreads();
        CLUSTER_SYNC();
    }

    // emission pointers for this thread's 2 own states x 2 batches
    const float* pn0 = inputs + (size_t)(bb + n0) * TT * NS;
    const float* pn1 = inputs + (size_t)(bb + n1) * TT * NS;

    float emA[4], emB[4];
    {
        const float* q0 = pn0 + (size_t)1 * NS;
        const float* q1 = pn1 + (size_t)1 * NS;
        emA[0] = q0[r0s]; emA[1] = q1[r0s]; emA[2] = q0[r1s]; emA[3] = q1[r1s];
    }
    {
        const float* q0 = pn0 + (size_t)2 * NS;
        const float* q1 = pn1 + (size_t)2 * NS;
        emB[0] = q0[r0s]; emB[1] = q1[r0s]; emB[2] = q0[r1s]; emB[3] = q1[r1s];
    }

    int ksum0 = 0, ksum1 = 0;
    uint32_t cur = 0;
    uint32_t ph[2] = {0u, 0u};
    const int own0 = (int)rank * 8;        // own kt range base (phys cols)
    const int pk0  = 8 - (int)rank * 8;    // peer kt range base
    // own-half store word: phys pair index 8*wid+gidr within half
    const uint32_t stoff = rank * 256u + (uint32_t)((8 * wid + gidr) * 4);

    for (int t = 1; t < TT; t++) {
        const uint32_t bufb = smem_base + SM_EA + cur * EABUF;
        const uint32_t bbase = bufb + (uint32_t)(gidr * RSB + tig * 4);

        // own-half B loads (data guaranteed by local syncthreads)
        uint32_t Bw[16];
#pragma unroll
        for (int k = 0; k < 8; k++) {
            uint32_t ad = bbase + (uint32_t)((own0 + k) * 32);
            asm volatile("ld.shared.b32 %0,[%1];" : "=r"(Bw[2 * k]) : "r"(ad));
            asm volatile("ld.shared.b32 %0,[%1];" : "=r"(Bw[2 * k + 1]) : "r"(ad + 16));
        }

        // hoisted scalars (no invM yet)
        uint32_t mw = masksS[t - 1];
        float esr0 = __expf(emA[0]);
        float esr1 = __expf(emA[1]);
        float esr2 = __expf(emA[2]);
        float esr3 = __expf(emA[3]);
#pragma unroll
        for (int i = 0; i < 4; i++) emA[i] = emB[i];
        if (t + 2 < TT) {
            const float* q0 = pn0 + (size_t)(t + 2) * NS;
            const float* q1 = pn1 + (size_t)(t + 2) * NS;
            emB[0] = q0[r0s]; emB[1] = q1[r0s]; emB[2] = q0[r1s]; emB[3] = q1[r1s];
        }

        // MMA own half (2 chains by kt parity)
        float de[4] = {0.f, 0.f, 0.f, 0.f}, dodd[4] = {0.f, 0.f, 0.f, 0.f};
#pragma unroll
        for (int k = 0; k < 8; k++) {
            if (k & 1) MMA_BF16(dodd, A[own0 + k], Bw[2 * k], Bw[2 * k + 1]);
            else       MMA_BF16(de,   A[own0 + k], Bw[2 * k], Bw[2 * k + 1]);
        }

        // wait for peer half (arrived via DSMEM; overlapped with own-half MMA)
        if (t > 1) {
            uint32_t ba = cur ? bar1 : bar0;
            MBAR_WAIT_CL(ba, ph[cur]);
            ph[cur] ^= 1u;
        }

        // renorm probe: state 0 bf16 at phys byte 0 (valid in both ranks now)
        uint32_t v0p, v1p;
        asm volatile("ld.shared.u16 %0,[%1];" : "=r"(v0p) : "r"(bufb + (uint32_t)(n0 * RSB)));
        asm volatile("ld.shared.u16 %0,[%1];" : "=r"(v1p) : "r"(bufb + (uint32_t)(n1 * RSB)));
        uint32_t e0b = (v0p >> 7) & 0xFFu;
        uint32_t e1b = (v1p >> 7) & 0xFFu;
        ksum0 += (int)e0b - 127;
        ksum1 += (int)e1b - 127;
        float invM0 = __uint_as_float((254u - e0b) << 23);
        float invM1 = __uint_as_float((254u - e1b) << 23);
        float es0 = esr0 * invM0, es1 = esr1 * invM1;
        float es2 = esr2 * invM0, es3 = esr3 * invM1;

        // peer-half B loads + MMA
#pragma unroll
        for (int k = 0; k < 8; k++) {
            uint32_t ad = bbase + (uint32_t)((pk0 + k) * 32);
            asm volatile("ld.shared.b32 %0,[%1];" : "=r"(Bw[2 * k]) : "r"(ad));
            asm volatile("ld.shared.b32 %0,[%1];" : "=r"(Bw[2 * k + 1]) : "r"(ad + 16));
        }
#pragma unroll
        for (int k = 0; k < 8; k++) {
            if (k & 1) MMA_BF16(dodd, A[pk0 + k], Bw[2 * k], Bw[2 * k + 1]);
            else       MMA_BF16(de,   A[pk0 + k], Bw[2 * k], Bw[2 * k + 1]);
        }

        // rare masked path: per-batch sums of current full ea
        float Sv0 = 0.f, Sv1 = 0.f;
        if (mw != 0xFFu) {
            float s = 0.f;
#pragma unroll
            for (int q = 0; q < 4; q++) {
                uint32_t v;
                uint32_t ad = bufb + (uint32_t)(wid * RSB + (lane * 4 + q) * 4);
                asm volatile("ld.shared.b32 %0,[%1];" : "=r"(v) : "r"(ad));
                s += __uint_as_float(v << 16) + __uint_as_float(v & 0xFFFF0000u);
            }
#pragma unroll
            for (int o = 16; o; o >>= 1) s += __shfl_xor_sync(~0u, s, o);
            if (lane == 0) Ssm[wid] = s;
            __syncthreads();
            Sv0 = Ssm[n0] * invM0;
            Sv1 = Ssm[n1] * invM1;
        }

        // epilogue: u = d*es ; store bf16x2 locally AND to peer via DSMEM
        const uint32_t nxtb = smem_base + SM_EA + (cur ^ 1u) * EABUF;
        float u00 = (de[0] + dodd[0]) * es0;  // (r0s, n0)
        float u01 = (de[1] + dodd[1]) * es1;  // (r0s, n1)
        float u02 = (de[2] + dodd[2]) * es2;  // (r1s, n0)
        float u03 = (de[3] + dodd[3]) * es3;  // (r1s, n1)
        if (mw != 0xFFu) {
            if (!((mw >> n0) & 1u)) { u00 = Sv0; u02 = Sv0; }
            if (!((mw >> n1) & 1u)) { u01 = Sv1; u03 = Sv1; }
        }
        {
            uint32_t w0, w1;
            asm volatile("cvt.rn.bf16x2.f32 %0, %1, %2;" : "=r"(w0) : "f"(u02), "f"(u00));
            asm volatile("cvt.rn.bf16x2.f32 %0, %1, %2;" : "=r"(w1) : "f"(u03), "f"(u01));
            uint32_t a0 = nxtb + (uint32_t)(n0 * RSB) + stoff;
            uint32_t a1 = nxtb + (uint32_t)(n1 * RSB) + stoff;
            asm volatile("st.shared.b32 [%0], %1;" :: "r"(a0), "r"(w0));
            asm volatile("st.shared.b32 [%0], %1;" :: "r"(a1), "r"(w1));
            st_remote_b32(a0, peer, w0);
            st_remote_b32(a1, peer, w1);
        }
        __syncthreads();
        if (tid == 0) {
            asm volatile("fence.acq_rel.cluster;" ::: "memory");
            mbar_arrive_remote((cur ^ 1u) ? bar1 : bar0, peer);
        }
        cur ^= 1u;
    }

    // final: cluster sync makes peer's last remote stores visible
    CLUSTER_SYNC();
    {
        int st = permf(tid);
        float ets = __expf(trans[STOP_TAG * NS + st]);
        const uint32_t bufb = smem_base + SM_EA + cur * EABUF;
        float v[NB];
#pragma unroll
        for (int n = 0; n < NB; n++) {
            uint32_t hv;
            uint32_t ad = bufb + (uint32_t)(n * RSB + tid * 2);
            asm volatile("ld.shared.u16 %0,[%1];" : "=r"(hv) : "r"(ad));
            v[n] = __uint_as_float(hv << 16) * ets;
        }
        __syncthreads();
#pragma unroll
        for (int n = 0; n < NB; n++) {
            float s = v[n];
#pragma unroll
            for (int o = 16; o; o >>= 1) s += __shfl_xor_sync(~0u, s, o);
            if (lane == 0) redsm[wid * 8 + n] = s;
        }
        if (tid < 4) { kssm[n0] = ksum0; kssm[n1] = ksum1; }
        __syncthreads();
        if (tid < 8 && rank == 0) {
            float s = 0.f;
#pragma unroll
            for (int w = 0; w < 8; w++) s += redsm[w * 8 + tid];
            g_den[bb + tid] = C0sm[tid] + (float)kssm[tid] * LN2F + __logf(s);
        }
    }
    CLUSTER_SYNC();
}

// ---------------------------------------------------------------------------
// Numerator: 1 warp per batch
// ---------------------------------------------------------------------------
__global__ void num_kernel(const float* __restrict__ inputs,
                           const float* __restrict__ trans,
                           const int* __restrict__ tags,
                           const int* __restrict__ mask)
{
    int b = blockIdx.x;
    int lane = threadIdx.x;
    const int* tg = tags + b * TT;
    const int* mk = mask + b * TT;
    float sc = 0.f;
    int mc = 0;
    for (int t = lane; t < TT; t += 32) {
        int tgt = tg[t];
        int m = mk[t];
        mc += m;
        if (t >= 1) sc += trans[tgt * NS + tg[t - 1]] * (float)m;
        if (t < TT - 1) sc += inputs[((size_t)b * TT + t) * NS + tgt] * (float)m;
    }
#pragma unroll
    for (int o = 16; o; o >>= 1) {
        sc += __shfl_xor_sync(0xffffffffu, sc, o);
        mc += __shfl_xor_sync(0xffffffffu, mc, o);
    }
    if (lane == 0) {
        sc += trans[tg[0] * NS + START_TAG];
        int li = mc - 1;
        if (li < 0) li = 0;
        int lt = tg[li];
        sc += trans[STOP_TAG * NS + lt]
            + inputs[((size_t)b * TT + (TT - 1)) * NS + lt] * (float)mk[TT - 1];
        g_num[b] = sc;
    }
}

// ---------------------------------------------------------------------------
// Final reduce: sum_b (num - den)
// ---------------------------------------------------------------------------
__global__ void final_kernel(float* __restrict__ out)
{
    __shared__ float red[8];
    int tid = threadIdx.x;
    int lane = tid & 31, wid = tid >> 5;
    float v = g_num[tid] - g_den[tid];
#pragma unroll
    for (int o = 16; o; o >>= 1) v += __shfl_xor_sync(0xffffffffu, v, o);
    if (lane == 0) red[wid] = v;
    __syncthreads();
    if (tid == 0) {
        float s = 0.f;
#pragma unroll
        for (int w = 0; w < 8; w++) s += red[w];
        out[0] = s;
    }
}

extern "C" void kernel_launch(void* const* d_in, const int* in_sizes, int n_in,
                              void* d_out, int out_size)
{
    const float* inputs = (const float*)d_in[0];
    const float* trans  = (const float*)d_in[1];
    const int*   tags   = (const int*)d_in[2];
    const int*   mask   = (const int*)d_in[3];

    prep_kernel<<<256, 256>>>(trans);
    forward_kernel<<<NCTA_G, 256>>>(inputs, trans, mask);
    num_kernel<<<BB, 32>>>(inputs, trans, tags, mask);
    final_kernel<<<1, 256>>>((float*)d_out);
}

// round 14
// speedup vs baseline: 1.1936x; 1.1936x over previous
#include <cuda_runtime.h>
#include <cuda_bf16.h>
#include <cstdint>

#define BB 256
#define TT 512
#define NS 256
#define START_TAG 254
#define STOP_TAG 255
#define LN2F 0.6931471805599453f
#define NB 16
#define NCTA (BB / NB)         // 16 CTAs, 2 groups of 8 batches each
#define RSB 528                // ea row stride bytes (132 words -> conflict-free)
#define EABUF (NB * RSB)       // 8448

// scratch (allocation-free rule: __device__ globals)
__device__ float g_den[BB];
__device__ float g_num[BB];
// E = exp(trans) bf16, columns PRE-PERMUTED: g_Ebf[r*256+x] = exp(trans[r][perm(x)])
// perm(x) = 32*(x>>5) + ((x>>2)&7) + 8*(x&3)
__device__ unsigned short g_Ebf[NS * NS];

__device__ __forceinline__ int permf(int x) {
    return 32 * (x >> 5) + ((x >> 2) & 7) + 8 * (x & 3);
}
__device__ __forceinline__ int iperm(int s) {
    return 32 * (s >> 5) + 4 * (s & 7) + ((s >> 3) & 3);
}

// ---------------------------------------------------------------------------
// smem layout (static, ~19.3 KB)
// ---------------------------------------------------------------------------
#define SM_EA    0        // 2 x 8448 ea double buffer: [n][x] bf16 (16 rows)
#define SM_MASK  16896    // 512 u32 mask bitfields (16 bits each)
#define SM_MSLOT 18944    // 2 x 16 floats (state-0 value per batch, renorm probe)
#define SM_C0    19072    // 16 floats
#define SM_RED   19136    // 128 floats (8 warps x 16)
#define SM_KS    19648    // 16 ints
#define SM_SS    19712    // 16 floats
#define SM_TOTAL 19776

#define MMA_BF16(d, a, b0, b1) \
    asm volatile( \
        "mma.sync.aligned.m16n8k16.row.col.f32.bf16.bf16.f32 " \
        "{%0,%1,%2,%3},{%4,%5,%6,%7},{%8,%9},{%0,%1,%2,%3};" \
        : "+f"((d)[0]), "+f"((d)[1]), "+f"((d)[2]), "+f"((d)[3]) \
        : "r"((a)[0]), "r"((a)[1]), "r"((a)[2]), "r"((a)[3]), "r"(b0), "r"(b1))

// ---------------------------------------------------------------------------
// Prep: permuted bf16 E
// ---------------------------------------------------------------------------
__global__ void prep_kernel(const float* __restrict__ trans) {
    int gid = blockIdx.x * blockDim.x + threadIdx.x;  // 0..65535
    int r = gid >> 8, x = gid & 255;
    g_Ebf[gid] = __bfloat16_as_ushort(__float2bfloat16(__expf(trans[r * NS + permf(x)])));
}

// ---------------------------------------------------------------------------
// Forward recursion via mma.sync bf16: TWO 8-batch groups per CTA sharing the
// register-resident A fragments; one barrier per double-step.
// ---------------------------------------------------------------------------
__global__ void __launch_bounds__(256, 1) forward_kernel(
    const float* __restrict__ inputs,
    const float* __restrict__ trans,
    const int* __restrict__ mask)
{
    __shared__ __align__(16) char smem[SM_TOTAL];
    const uint32_t smem_base = (uint32_t)__cvta_generic_to_shared(smem);
    float*    mslotF = (float*)(smem + SM_MSLOT);
    uint32_t* masksS = (uint32_t*)(smem + SM_MASK);
    float*    C0sm   = (float*)(smem + SM_C0);
    float*    redsm  = (float*)(smem + SM_RED);
    int*      kssm   = (int*)(smem + SM_KS);
    float*    Ssm    = (float*)(smem + SM_SS);

    const int tid  = threadIdx.x;
    const int lane = tid & 31;
    const int wid  = tid >> 5;
    const int gidr = lane >> 2;   // groupID
    const int tig  = lane & 3;    // thread-in-group
    const int wbase = wid * 32;   // warp's state base
    const int bb    = blockIdx.x * NB;
    const int n0 = 2 * tig, n1 = n0 + 1;          // group A batch rows
    const int n2 = n0 + 8, n3 = n1 + 8;           // group B batch rows

    // mask bitfields (16 bits)
    for (int tt = tid; tt < TT; tt += 256) {
        uint32_t w = 0;
#pragma unroll
        for (int n = 0; n < NB; n++) w |= (mask[(bb + n) * TT + tt] ? 1u : 0u) << n;
        masksS[tt] = w;
    }

    // A fragments from permuted E (128 u32/thread, shared by both groups)
    uint32_t A[2][16][4];
    {
#pragma unroll
        for (int mt = 0; mt < 2; mt++) {
            int r0 = wbase + mt * 16 + gidr, r1 = r0 + 8;
#pragma unroll
            for (int kt = 0; kt < 16; kt++) {
                int c0 = kt * 16 + tig * 2;
                A[mt][kt][0] = *(const uint32_t*)&g_Ebf[r0 * NS + c0];
                A[mt][kt][1] = *(const uint32_t*)&g_Ebf[r1 * NS + c0];
                A[mt][kt][2] = *(const uint32_t*)&g_Ebf[r0 * NS + c0 + 8];
                A[mt][kt][3] = *(const uint32_t*)&g_Ebf[r1 * NS + c0 + 8];
            }
        }
    }

    // alpha0: per-batch max -> C0; ea0 at physical iperm(state)
    {
        float a0v[NB];
        float tS = trans[tid * NS + START_TAG];
#pragma unroll
        for (int n = 0; n < NB; n++)
            a0v[n] = tS + inputs[((size_t)(bb + n) * TT) * NS + tid];
#pragma unroll
        for (int n = 0; n < NB; n++) {
            float m = a0v[n];
#pragma unroll
            for (int o = 16; o; o >>= 1) m = fmaxf(m, __shfl_xor_sync(~0u, m, o));
            if (lane == 0) redsm[wid * 16 + n] = m;
        }
        __syncthreads();
        if (tid < NB) {
            float m = -INFINITY;
#pragma unroll
            for (int w = 0; w < 8; w++) m = fmaxf(m, redsm[w * 16 + tid]);
            C0sm[tid] = m;
        }
        __syncthreads();
        int xph = iperm(tid);
#pragma unroll
        for (int n = 0; n < NB; n++) {
            float e = __expf(a0v[n] - C0sm[n]);
            unsigned short h = __bfloat16_as_ushort(__float2bfloat16(e));
            uint32_t ad = smem_base + SM_EA + (uint32_t)(n * RSB + xph * 2);
            asm volatile("st.shared.b16 [%0], %1;" :: "r"(ad), "h"(h));
            if (tid == 0) mslotF[n] = e;
        }
        __syncthreads();
    }

    // emission pointers (4 logical states x 4 batch rows)
    const float* pA0 = inputs + (size_t)(bb + n0) * TT * NS;
    const float* pA1 = inputs + (size_t)(bb + n1) * TT * NS;
    const float* pB0 = inputs + (size_t)(bb + n2) * TT * NS;
    const float* pB1 = inputs + (size_t)(bb + n3) * TT * NS;
    const int m00 = wbase + gidr, m01 = m00 + 8, m10 = m00 + 16, m11 = m00 + 24;

    float em[16];
    {
        const float* qA0 = pA0 + (size_t)1 * NS;
        const float* qA1 = pA1 + (size_t)1 * NS;
        const float* qB0 = pB0 + (size_t)1 * NS;
        const float* qB1 = pB1 + (size_t)1 * NS;
        em[0] = qA0[m00]; em[1] = qA1[m00]; em[2] = qA0[m01]; em[3] = qA1[m01];
        em[4] = qA0[m10]; em[5] = qA1[m10]; em[6] = qA0[m11]; em[7] = qA1[m11];
        em[8] = qB0[m00]; em[9] = qB1[m00]; em[10] = qB0[m01]; em[11] = qB1[m01];
        em[12] = qB0[m10]; em[13] = qB1[m10]; em[14] = qB0[m11]; em[15] = qB1[m11];
    }

    int ksum0 = 0, ksum1 = 0, ksum2 = 0, ksum3 = 0;
    uint32_t cur = 0;
    const uint32_t stoff = (uint32_t)((wbase + 4 * gidr) * 2);

    for (int t = 1; t < TT; t++) {
        const uint32_t bufb = smem_base + SM_EA + cur * EABUF;
        const uint32_t bbaseA = bufb + (uint32_t)(gidr * RSB + tig * 4);
        const uint32_t bbaseB = bbaseA + 8u * RSB;

        // ---- group A first-half B-loads (pairs at kt*32 and kt*32+16) ----
        uint32_t Bw[16];
#pragma unroll
        for (int k = 0; k < 8; k++) {
            uint32_t ad = bbaseA + (uint32_t)(k * 32);
            asm volatile("ld.shared.b32 %0,[%1];" : "=r"(Bw[2 * k]) : "r"(ad));
            asm volatile("ld.shared.b32 %0,[%1];" : "=r"(Bw[2 * k + 1]) : "r"(ad + 16));
        }

        // ---- hoisted scalars: renorm (stale state-0), mask, es = exp(em)*invM
        float ms0 = mslotF[cur * 16 + n0];
        float ms1 = mslotF[cur * 16 + n1];
        float ms2 = mslotF[cur * 16 + n2];
        float ms3 = mslotF[cur * 16 + n3];
        uint32_t mw = masksS[t - 1];
        uint32_t e0b = (__float_as_uint(ms0) >> 23) & 0xFFu;
        uint32_t e1b = (__float_as_uint(ms1) >> 23) & 0xFFu;
        uint32_t e2b = (__float_as_uint(ms2) >> 23) & 0xFFu;
        uint32_t e3b = (__float_as_uint(ms3) >> 23) & 0xFFu;
        ksum0 += (int)e0b - 127;
        ksum1 += (int)e1b - 127;
        ksum2 += (int)e2b - 127;
        ksum3 += (int)e3b - 127;
        float invM0 = __uint_as_float((254u - e0b) << 23);
        float invM1 = __uint_as_float((254u - e1b) << 23);
        float invM2 = __uint_as_float((254u - e2b) << 23);
        float invM3 = __uint_as_float((254u - e3b) << 23);
        float es[16];
#pragma unroll
        for (int i = 0; i < 8; i += 2) {
            es[i]     = __expf(em[i]) * invM0;
            es[i + 1] = __expf(em[i + 1]) * invM1;
            es[8 + i]     = __expf(em[8 + i]) * invM2;
            es[8 + i + 1] = __expf(em[8 + i + 1]) * invM3;
        }

        // ---- group A MMA: 32 HMMA in 4 chains ----
        float a0e[4] = {0.f, 0.f, 0.f, 0.f}, a0o[4] = {0.f, 0.f, 0.f, 0.f};
        float a1e[4] = {0.f, 0.f, 0.f, 0.f}, a1o[4] = {0.f, 0.f, 0.f, 0.f};
#pragma unroll
        for (int k = 0; k < 8; k++) {
            if (k & 1) {
                MMA_BF16(a0o, A[0][k], Bw[2 * k], Bw[2 * k + 1]);
                MMA_BF16(a1o, A[1][k], Bw[2 * k], Bw[2 * k + 1]);
            } else {
                MMA_BF16(a0e, A[0][k], Bw[2 * k], Bw[2 * k + 1]);
                MMA_BF16(a1e, A[1][k], Bw[2 * k], Bw[2 * k + 1]);
            }
        }
        uint32_t Bw2[16];
#pragma unroll
        for (int k = 0; k < 8; k++) {
            uint32_t ad = bbaseA + (uint32_t)((8 + k) * 32);
            asm volatile("ld.shared.b32 %0,[%1];" : "=r"(Bw2[2 * k]) : "r"(ad));
            asm volatile("ld.shared.b32 %0,[%1];" : "=r"(Bw2[2 * k + 1]) : "r"(ad + 16));
        }
#pragma unroll
        for (int k = 0; k < 8; k++) {
            int kt = 8 + k;
            if (k & 1) {
                MMA_BF16(a0o, A[0][kt], Bw2[2 * k], Bw2[2 * k + 1]);
                MMA_BF16(a1o, A[1][kt], Bw2[2 * k], Bw2[2 * k + 1]);
            } else {
                MMA_BF16(a0e, A[0][kt], Bw2[2 * k], Bw2[2 * k + 1]);
                MMA_BF16(a1e, A[1][kt], Bw2[2 * k], Bw2[2 * k + 1]);
            }
        }

        // ---- group B loads + MMA (hides A's D latency) ----
        float b0e[4] = {0.f, 0.f, 0.f, 0.f}, b0o[4] = {0.f, 0.f, 0.f, 0.f};
        float b1e[4] = {0.f, 0.f, 0.f, 0.f}, b1o[4] = {0.f, 0.f, 0.f, 0.f};
#pragma unroll
        for (int k = 0; k < 8; k++) {
            uint32_t ad = bbaseB + (uint32_t)(k * 32);
            asm volatile("ld.shared.b32 %0,[%1];" : "=r"(Bw[2 * k]) : "r"(ad));
            asm volatile("ld.shared.b32 %0,[%1];" : "=r"(Bw[2 * k + 1]) : "r"(ad + 16));
        }
#pragma unroll
        for (int k = 0; k < 8; k++) {
            if (k & 1) {
                MMA_BF16(b0o, A[0][k], Bw[2 * k], Bw[2 * k + 1]);
                MMA_BF16(b1o, A[1][k], Bw[2 * k], Bw[2 * k + 1]);
            } else {
                MMA_BF16(b0e, A[0][k], Bw[2 * k], Bw[2 * k + 1]);
                MMA_BF16(b1e, A[1][k], Bw[2 * k], Bw[2 * k + 1]);
            }
        }
#pragma unroll
        for (int k = 0; k < 8; k++) {
            uint32_t ad = bbaseB + (uint32_t)((8 + k) * 32);
            asm volatile("ld.shared.b32 %0,[%1];" : "=r"(Bw2[2 * k]) : "r"(ad));
            asm volatile("ld.shared.b32 %0,[%1];" : "=r"(Bw2[2 * k + 1]) : "r"(ad + 16));
        }
#pragma unroll
        for (int k = 0; k < 8; k++) {
            int kt = 8 + k;
            if (k & 1) {
                MMA_BF16(b0o, A[0][kt], Bw2[2 * k], Bw2[2 * k + 1]);
                MMA_BF16(b1o, A[1][kt], Bw2[2 * k], Bw2[2 * k + 1]);
            } else {
                MMA_BF16(b0e, A[0][kt], Bw2[2 * k], Bw2[2 * k + 1]);
                MMA_BF16(b1e, A[1][kt], Bw2[2 * k], Bw2[2 * k + 1]);
            }
        }

        // mid-iteration: reload em for t+1 (arrives well before next use)
        if (t + 1 < TT) {
            const float* qA0 = pA0 + (size_t)(t + 1) * NS;
            const float* qA1 = pA1 + (size_t)(t + 1) * NS;
            const float* qB0 = pB0 + (size_t)(t + 1) * NS;
            const float* qB1 = pB1 + (size_t)(t + 1) * NS;
            em[0] = qA0[m00]; em[1] = qA1[m00]; em[2] = qA0[m01]; em[3] = qA1[m01];
            em[4] = qA0[m10]; em[5] = qA1[m10]; em[6] = qA0[m11]; em[7] = qA1[m11];
            em[8] = qB0[m00]; em[9] = qB1[m00]; em[10] = qB0[m01]; em[11] = qB1[m01];
            em[12] = qB0[m10]; em[13] = qB1[m10]; em[14] = qB0[m11]; em[15] = qB1[m11];
        }

        // rare masked path: per-batch sums of current ea (all 16 rows)
        float Sv0 = 0.f, Sv1 = 0.f, Sv2 = 0.f, Sv3 = 0.f;
        if (mw != 0xFFFFu) {
            float sA = 0.f, sB = 0.f;
#pragma unroll
            for (int q = 0; q < 4; q++) {
                uint32_t v;
                uint32_t ad = bufb + (uint32_t)(wid * RSB + (lane * 4 + q) * 4);
                asm volatile("ld.shared.b32 %0,[%1];" : "=r"(v) : "r"(ad));
                sA += __uint_as_float(v << 16) + __uint_as_float(v & 0xFFFF0000u);
                uint32_t ad2 = ad + 8u * RSB;
                asm volatile("ld.shared.b32 %0,[%1];" : "=r"(v) : "r"(ad2));
                sB += __uint_as_float(v << 16) + __uint_as_float(v & 0xFFFF0000u);
            }
#pragma unroll
            for (int o = 16; o; o >>= 1) {
                sA += __shfl_xor_sync(~0u, sA, o);
                sB += __shfl_xor_sync(~0u, sB, o);
            }
            if (lane == 0) { Ssm[wid] = sA; Ssm[wid + 8] = sB; }
            __syncthreads();
            Sv0 = Ssm[n0] * invM0;
            Sv1 = Ssm[n1] * invM1;
            Sv2 = Ssm[n2] * invM2;
            Sv3 = Ssm[n3] * invM3;
        }

        const uint32_t nxtb = smem_base + SM_EA + (cur ^ 1u) * EABUF;

        // ---- epilogue A ----
        {
            float u00 = (a0e[0] + a0o[0]) * es[0], u01 = (a0e[1] + a0o[1]) * es[1];
            float u02 = (a0e[2] + a0o[2]) * es[2], u03 = (a0e[3] + a0o[3]) * es[3];
            float u10 = (a1e[0] + a1o[0]) * es[4], u11 = (a1e[1] + a1o[1]) * es[5];
            float u12 = (a1e[2] + a1o[2]) * es[6], u13 = (a1e[3] + a1o[3]) * es[7];
            if (mw != 0xFFFFu) {
                if (!((mw >> n0) & 1u)) { u00 = Sv0; u02 = Sv0; u10 = Sv0; u12 = Sv0; }
                if (!((mw >> n1) & 1u)) { u01 = Sv1; u03 = Sv1; u11 = Sv1; u13 = Sv1; }
            }
            uint32_t w0, w1, w2, w3;
            asm volatile("cvt.rn.bf16x2.f32 %0, %1, %2;" : "=r"(w0) : "f"(u02), "f"(u00));
            asm volatile("cvt.rn.bf16x2.f32 %0, %1, %2;" : "=r"(w1) : "f"(u12), "f"(u10));
            asm volatile("cvt.rn.bf16x2.f32 %0, %1, %2;" : "=r"(w2) : "f"(u03), "f"(u01));
            asm volatile("cvt.rn.bf16x2.f32 %0, %1, %2;" : "=r"(w3) : "f"(u13), "f"(u11));
            uint32_t a0 = nxtb + (uint32_t)(n0 * RSB) + stoff;
            uint32_t a1 = nxtb + (uint32_t)(n1 * RSB) + stoff;
            asm volatile("st.shared.v2.b32 [%0], {%1,%2};" :: "r"(a0), "r"(w0), "r"(w1));
            asm volatile("st.shared.v2.b32 [%0], {%1,%2};" :: "r"(a1), "r"(w2), "r"(w3));
            if (tid < 4) {
                mslotF[(cur ^ 1u) * 16 + n0] = u00;
                mslotF[(cur ^ 1u) * 16 + n1] = u01;
            }
        }
        // ---- epilogue B ----
        {
            float u00 = (b0e[0] + b0o[0]) * es[8],  u01 = (b0e[1] + b0o[1]) * es[9];
            float u02 = (b0e[2] + b0o[2]) * es[10], u03 = (b0e[3] + b0o[3]) * es[11];
            float u10 = (b1e[0] + b1o[0]) * es[12], u11 = (b1e[1] + b1o[1]) * es[13];
            float u12 = (b1e[2] + b1o[2]) * es[14], u13 = (b1e[3] + b1o[3]) * es[15];
            if (mw != 0xFFFFu) {
                if (!((mw >> n2) & 1u)) { u00 = Sv2; u02 = Sv2; u10 = Sv2; u12 = Sv2; }
                if (!((mw >> n3) & 1u)) { u01 = Sv3; u03 = Sv3; u11 = Sv3; u13 = Sv3; }
            }
            uint32_t w0, w1, w2, w3;
            asm volatile("cvt.rn.bf16x2.f32 %0, %1, %2;" : "=r"(w0) : "f"(u02), "f"(u00));
            asm volatile("cvt.rn.bf16x2.f32 %0, %1, %2;" : "=r"(w1) : "f"(u12), "f"(u10));
            asm volatile("cvt.rn.bf16x2.f32 %0, %1, %2;" : "=r"(w2) : "f"(u03), "f"(u01));
            asm volatile("cvt.rn.bf16x2.f32 %0, %1, %2;" : "=r"(w3) : "f"(u13), "f"(u11));
            uint32_t a0 = nxtb + (uint32_t)(n2 * RSB) + stoff;
            uint32_t a1 = nxtb + (uint32_t)(n3 * RSB) + stoff;
            asm volatile("st.shared.v2.b32 [%0], {%1,%2};" :: "r"(a0), "r"(w0), "r"(w1));
            asm volatile("st.shared.v2.b32 [%0], {%1,%2};" :: "r"(a1), "r"(w2), "r"(w3));
            if (tid < 4) {
                mslotF[(cur ^ 1u) * 16 + n2] = u00;
                mslotF[(cur ^ 1u) * 16 + n3] = u01;
            }
        }
        __syncthreads();
        cur ^= 1u;
    }

    // epilogue: den[b] = C0 + ksum*ln2 + log(sum ea * exp(trans[STOP,.]))
    {
        int st = permf(tid);
        float ets = __expf(trans[STOP_TAG * NS + st]);
        const uint32_t bufb = smem_base + SM_EA + cur * EABUF;
        float v[NB];
#pragma unroll
        for (int n = 0; n < NB; n++) {
            uint32_t hv;
            uint32_t ad = bufb + (uint32_t)(n * RSB + tid * 2);
            asm volatile("ld.shared.u16 %0,[%1];" : "=r"(hv) : "r"(ad));
            v[n] = __uint_as_float(hv << 16) * ets;
        }
#pragma unroll
        for (int n = 0; n < NB; n++) {
            float s = v[n];
#pragma unroll
            for (int o = 16; o; o >>= 1) s += __shfl_xor_sync(~0u, s, o);
            if (lane == 0) redsm[wid * 16 + n] = s;
        }
        if (tid < 4) {
            kssm[n0] = ksum0; kssm[n1] = ksum1;
            kssm[n2] = ksum2; kssm[n3] = ksum3;
        }
        __syncthreads();
        if (tid < NB) {
            float s = 0.f;
#pragma unroll
            for (int w = 0; w < 8; w++) s += redsm[w * 16 + tid];
            g_den[bb + tid] = C0sm[tid] + (float)kssm[tid] * LN2F + __logf(s);
        }
    }
}

// ---------------------------------------------------------------------------
// Numerator: 1 warp per batch
// ---------------------------------------------------------------------------
__global__ void num_kernel(const float* __restrict__ inputs,
                           const float* __restrict__ trans,
                           const int* __restrict__ tags,
                           const int* __restrict__ mask)
{
    int b = blockIdx.x;
    int lane = threadIdx.x;
    const int* tg = tags + b * TT;
    const int* mk = mask + b * TT;
    float sc = 0.f;
    int mc = 0;
    for (int t = lane; t < TT; t += 32) {
        int tgt = tg[t];
        int m = mk[t];
        mc += m;
        if (t >= 1) sc += trans[tgt * NS + tg[t - 1]] * (float)m;
        if (t < TT - 1) sc += inputs[((size_t)b * TT + t) * NS + tgt] * (float)m;
    }
#pragma unroll
    for (int o = 16; o; o >>= 1) {
        sc += __shfl_xor_sync(0xffffffffu, sc, o);
        mc += __shfl_xor_sync(0xffffffffu, mc, o);
    }
    if (lane == 0) {
        sc += trans[tg[0] * NS + START_TAG];
        int li = mc - 1;
        if (li < 0) li = 0;
        int lt = tg[li];
        sc += trans[STOP_TAG * NS + lt]
            + inputs[((size_t)b * TT + (TT - 1)) * NS + lt] * (float)mk[TT - 1];
        g_num[b] = sc;
    }
}

// ---------------------------------------------------------------------------
// Final reduce: sum_b (num - den)
// ---------------------------------------------------------------------------
__global__ void final_kernel(float* __restrict__ out)
{
    __shared__ float red[8];
    int tid = threadIdx.x;
    int lane = tid & 31, wid = tid >> 5;
    float v = g_num[tid] - g_den[tid];
#pragma unroll
    for (int o = 16; o; o >>= 1) v += __shfl_xor_sync(0xffffffffu, v, o);
    if (lane == 0) red[wid] = v;
    __syncthreads();
    if (tid == 0) {
        float s = 0.f;
#pragma unroll
        for (int w = 0; w < 8; w++) s += red[w];
        out[0] = s;
    }
}

extern "C" void kernel_launch(void* const* d_in, const int* in_sizes, int n_in,
                              void* d_out, int out_size)
{
    const float* inputs = (const float*)d_in[0];
    const float* trans  = (const float*)d_in[1];
    const int*   tags   = (const int*)d_in[2];
    const int*   mask   = (const int*)d_in[3];

    prep_kernel<<<256, 256>>>(trans);
    forward_kernel<<<NCTA, 256>>>(inputs, trans, mask);
    num_kernel<<<BB, 32>>>(inputs, trans, tags, mask);
    final_kernel<<<1, 256>>>((float*)d_out);
}

// round 15
// speedup vs baseline: 1.1945x; 1.0008x over previous
#include <cuda_runtime.h>
#include <cuda_bf16.h>
#include <cstdint>

#define BB 256
#define TT 512
#define NS 256
#define START_TAG 254
#define STOP_TAG 255
#define LN2F 0.6931471805599453f
#define NB 16
#define NCTA (BB / NB)         // 16 CTAs, 2 groups of 8 batches each
#define RSB 528                // ea row stride bytes (132 words -> conflict-free)
#define EABUF (NB * RSB)       // 8448

// scratch (allocation-free rule: __device__ globals)
__device__ float g_den[BB];
__device__ float g_num[BB];
// E = exp(trans) bf16, columns PRE-PERMUTED: g_Ebf[r*256+x] = exp(trans[r][perm(x)])
// perm(x) = 32*(x>>5) + ((x>>2)&7) + 8*(x&3)
__device__ unsigned short g_Ebf[NS * NS];

__device__ __forceinline__ int permf(int x) {
    return 32 * (x >> 5) + ((x >> 2) & 7) + 8 * (x & 3);
}
__device__ __forceinline__ int iperm(int s) {
    return 32 * (s >> 5) + 4 * (s & 7) + ((s >> 3) & 3);
}

// ---------------------------------------------------------------------------
// smem layout (static, ~19.3 KB)
// ---------------------------------------------------------------------------
#define SM_EA    0        // 2 x 8448 ea double buffer: [n][x] bf16 (16 rows)
#define SM_MASK  16896    // 512 u32 mask bitfields (16 bits each)
#define SM_MSLOT 18944    // 2 x 16 floats (state-0 value per batch, renorm probe)
#define SM_C0    19072    // 16 floats
#define SM_RED   19136    // 128 floats (8 warps x 16)
#define SM_KS    19648    // 16 ints
#define SM_SS    19712    // 16 floats
#define SM_TOTAL 19776

#define MMA_BF16(d, a, b0, b1) \
    asm volatile( \
        "mma.sync.aligned.m16n8k16.row.col.f32.bf16.bf16.f32 " \
        "{%0,%1,%2,%3},{%4,%5,%6,%7},{%8,%9},{%0,%1,%2,%3};" \
        : "+f"((d)[0]), "+f"((d)[1]), "+f"((d)[2]), "+f"((d)[3]) \
        : "r"((a)[0]), "r"((a)[1]), "r"((a)[2]), "r"((a)[3]), "r"(b0), "r"(b1))

// ---------------------------------------------------------------------------
// Prep: permuted bf16 E
// ---------------------------------------------------------------------------
__global__ void prep_kernel(const float* __restrict__ trans) {
    int gid = blockIdx.x * blockDim.x + threadIdx.x;  // 0..65535
    int r = gid >> 8, x = gid & 255;
    g_Ebf[gid] = __bfloat16_as_ushort(__float2bfloat16(__expf(trans[r * NS + permf(x)])));
}

// ---------------------------------------------------------------------------
// Forward recursion via mma.sync bf16: TWO 8-batch groups per CTA sharing the
// register-resident A fragments; one barrier per double-step.
// ---------------------------------------------------------------------------
__global__ void __launch_bounds__(256, 1) forward_kernel(
    const float* __restrict__ inputs,
    const float* __restrict__ trans,
    const int* __restrict__ mask)
{
    __shared__ __align__(16) char smem[SM_TOTAL];
    const uint32_t smem_base = (uint32_t)__cvta_generic_to_shared(smem);
    float*    mslotF = (float*)(smem + SM_MSLOT);
    uint32_t* masksS = (uint32_t*)(smem + SM_MASK);
    float*    C0sm   = (float*)(smem + SM_C0);
    float*    redsm  = (float*)(smem + SM_RED);
    int*      kssm   = (int*)(smem + SM_KS);
    float*    Ssm    = (float*)(smem + SM_SS);

    const int tid  = threadIdx.x;
    const int lane = tid & 31;
    const int wid  = tid >> 5;
    const int gidr = lane >> 2;   // groupID
    const int tig  = lane & 3;    // thread-in-group
    const int wbase = wid * 32;   // warp's state base
    const int bb    = blockIdx.x * NB;
    const int n0 = 2 * tig, n1 = n0 + 1;          // group A batch rows
    const int n2 = n0 + 8, n3 = n1 + 8;           // group B batch rows

    // mask bitfields (16 bits)
    for (int tt = tid; tt < TT; tt += 256) {
        uint32_t w = 0;
#pragma unroll
        for (int n = 0; n < NB; n++) w |= (mask[(bb + n) * TT + tt] ? 1u : 0u) << n;
        masksS[tt] = w;
    }

    // A fragments from permuted E (128 u32/thread, shared by both groups)
    uint32_t A[2][16][4];
    {
#pragma unroll
        for (int mt = 0; mt < 2; mt++) {
            int r0 = wbase + mt * 16 + gidr, r1 = r0 + 8;
#pragma unroll
            for (int kt = 0; kt < 16; kt++) {
                int c0 = kt * 16 + tig * 2;
                A[mt][kt][0] = *(const uint32_t*)&g_Ebf[r0 * NS + c0];
                A[mt][kt][1] = *(const uint32_t*)&g_Ebf[r1 * NS + c0];
                A[mt][kt][2] = *(const uint32_t*)&g_Ebf[r0 * NS + c0 + 8];
                A[mt][kt][3] = *(const uint32_t*)&g_Ebf[r1 * NS + c0 + 8];
            }
        }
    }

    // alpha0: per-batch max -> C0; ea0 at physical iperm(state)
    {
        float a0v[NB];
        float tS = trans[tid * NS + START_TAG];
#pragma unroll
        for (int n = 0; n < NB; n++)
            a0v[n] = tS + inputs[((size_t)(bb + n) * TT) * NS + tid];
#pragma unroll
        for (int n = 0; n < NB; n++) {
            float m = a0v[n];
#pragma unroll
            for (int o = 16; o; o >>= 1) m = fmaxf(m, __shfl_xor_sync(~0u, m, o));
            if (lane == 0) redsm[wid * 16 + n] = m;
        }
        __syncthreads();
        if (tid < NB) {
            float m = -INFINITY;
#pragma unroll
            for (int w = 0; w < 8; w++) m = fmaxf(m, redsm[w * 16 + tid]);
            C0sm[tid] = m;
        }
        __syncthreads();
        int xph = iperm(tid);
#pragma unroll
        for (int n = 0; n < NB; n++) {
            float e = __expf(a0v[n] - C0sm[n]);
            unsigned short h = __bfloat16_as_ushort(__float2bfloat16(e));
            uint32_t ad = smem_base + SM_EA + (uint32_t)(n * RSB + xph * 2);
            asm volatile("st.shared.b16 [%0], %1;" :: "r"(ad), "h"(h));
            if (tid == 0) mslotF[n] = e;
        }
        __syncthreads();
    }

    // emission pointers (4 logical states x 4 batch rows)
    const float* pA0 = inputs + (size_t)(bb + n0) * TT * NS;
    const float* pA1 = inputs + (size_t)(bb + n1) * TT * NS;
    const float* pB0 = inputs + (size_t)(bb + n2) * TT * NS;
    const float* pB1 = inputs + (size_t)(bb + n3) * TT * NS;
    const int m00 = wbase + gidr, m01 = m00 + 8, m10 = m00 + 16, m11 = m00 + 24;

    float em[16];
    {
        const float* qA0 = pA0 + (size_t)1 * NS;
        const float* qA1 = pA1 + (size_t)1 * NS;
        const float* qB0 = pB0 + (size_t)1 * NS;
        const float* qB1 = pB1 + (size_t)1 * NS;
        em[0] = qA0[m00]; em[1] = qA1[m00]; em[2] = qA0[m01]; em[3] = qA1[m01];
        em[4] = qA0[m10]; em[5] = qA1[m10]; em[6] = qA0[m11]; em[7] = qA1[m11];
        em[8] = qB0[m00]; em[9] = qB1[m00]; em[10] = qB0[m01]; em[11] = qB1[m01];
        em[12] = qB0[m10]; em[13] = qB1[m10]; em[14] = qB0[m11]; em[15] = qB1[m11];
    }

    int ksum0 = 0, ksum1 = 0, ksum2 = 0, ksum3 = 0;
    uint32_t cur = 0;
    const uint32_t stoff = (uint32_t)((wbase + 4 * gidr) * 2);

    for (int t = 1; t < TT; t++) {
        const uint32_t bufb = smem_base + SM_EA + cur * EABUF;
        const uint32_t bbaseA = bufb + (uint32_t)(gidr * RSB + tig * 4);
        const uint32_t bbaseB = bbaseA + 8u * RSB;

        // ---- group A first-half B-loads (pairs at kt*32 and kt*32+16) ----
        uint32_t Bw[16];
#pragma unroll
        for (int k = 0; k < 8; k++) {
            uint32_t ad = bbaseA + (uint32_t)(k * 32);
            asm volatile("ld.shared.b32 %0,[%1];" : "=r"(Bw[2 * k]) : "r"(ad));
            asm volatile("ld.shared.b32 %0,[%1];" : "=r"(Bw[2 * k + 1]) : "r"(ad + 16));
        }

        // ---- hoisted scalars: renorm (stale state-0), mask, es = exp(em)*invM
        float ms0 = mslotF[cur * 16 + n0];
        float ms1 = mslotF[cur * 16 + n1];
        float ms2 = mslotF[cur * 16 + n2];
        float ms3 = mslotF[cur * 16 + n3];
        uint32_t mw = masksS[t - 1];
        uint32_t e0b = (__float_as_uint(ms0) >> 23) & 0xFFu;
        uint32_t e1b = (__float_as_uint(ms1) >> 23) & 0xFFu;
        uint32_t e2b = (__float_as_uint(ms2) >> 23) & 0xFFu;
        uint32_t e3b = (__float_as_uint(ms3) >> 23) & 0xFFu;
        ksum0 += (int)e0b - 127;
        ksum1 += (int)e1b - 127;
        ksum2 += (int)e2b - 127;
        ksum3 += (int)e3b - 127;
        float invM0 = __uint_as_float((254u - e0b) << 23);
        float invM1 = __uint_as_float((254u - e1b) << 23);
        float invM2 = __uint_as_float((254u - e2b) << 23);
        float invM3 = __uint_as_float((254u - e3b) << 23);
        float es[16];
#pragma unroll
        for (int i = 0; i < 8; i += 2) {
            es[i]     = __expf(em[i]) * invM0;
            es[i + 1] = __expf(em[i + 1]) * invM1;
            es[8 + i]     = __expf(em[8 + i]) * invM2;
            es[8 + i + 1] = __expf(em[8 + i + 1]) * invM3;
        }

        // ---- group A MMA: 32 HMMA in 4 chains ----
        float a0e[4] = {0.f, 0.f, 0.f, 0.f}, a0o[4] = {0.f, 0.f, 0.f, 0.f};
        float a1e[4] = {0.f, 0.f, 0.f, 0.f}, a1o[4] = {0.f, 0.f, 0.f, 0.f};
#pragma unroll
        for (int k = 0; k < 8; k++) {
            if (k & 1) {
                MMA_BF16(a0o, A[0][k], Bw[2 * k], Bw[2 * k + 1]);
                MMA_BF16(a1o, A[1][k], Bw[2 * k], Bw[2 * k + 1]);
            } else {
                MMA_BF16(a0e, A[0][k], Bw[2 * k], Bw[2 * k + 1]);
                MMA_BF16(a1e, A[1][k], Bw[2 * k], Bw[2 * k + 1]);
            }
        }
        uint32_t Bw2[16];
#pragma unroll
        for (int k = 0; k < 8; k++) {
            uint32_t ad = bbaseA + (uint32_t)((8 + k) * 32);
            asm volatile("ld.shared.b32 %0,[%1];" : "=r"(Bw2[2 * k]) : "r"(ad));
            asm volatile("ld.shared.b32 %0,[%1];" : "=r"(Bw2[2 * k + 1]) : "r"(ad + 16));
        }
#pragma unroll
        for (int k = 0; k < 8; k++) {
            int kt = 8 + k;
            if (k & 1) {
                MMA_BF16(a0o, A[0][kt], Bw2[2 * k], Bw2[2 * k + 1]);
                MMA_BF16(a1o, A[1][kt], Bw2[2 * k], Bw2[2 * k + 1]);
            } else {
                MMA_BF16(a0e, A[0][kt], Bw2[2 * k], Bw2[2 * k + 1]);
                MMA_BF16(a1e, A[1][kt], Bw2[2 * k], Bw2[2 * k + 1]);
            }
        }

        // ---- group B loads + MMA (hides A's D latency) ----
        float b0e[4] = {0.f, 0.f, 0.f, 0.f}, b0o[4] = {0.f, 0.f, 0.f, 0.f};
        float b1e[4] = {0.f, 0.f, 0.f, 0.f}, b1o[4] = {0.f, 0.f, 0.f, 0.f};
#pragma unroll
        for (int k = 0; k < 8; k++) {
            uint32_t ad = bbaseB + (uint32_t)(k * 32);
            asm volatile("ld.shared.b32 %0,[%1];" : "=r"(Bw[2 * k]) : "r"(ad));
            asm volatile("ld.shared.b32 %0,[%1];" : "=r"(Bw[2 * k + 1]) : "r"(ad + 16));
        }
#pragma unroll
        for (int k = 0; k < 8; k++) {
            if (k & 1) {
                MMA_BF16(b0o, A[0][k], Bw[2 * k], Bw[2 * k + 1]);
                MMA_BF16(b1o, A[1][k], Bw[2 * k], Bw[2 * k + 1]);
            } else {
                MMA_BF16(b0e, A[0][k], Bw[2 * k], Bw[2 * k + 1]);
                MMA_BF16(b1e, A[1][k], Bw[2 * k], Bw[2 * k + 1]);
            }
        }
#pragma unroll
        for (int k = 0; k < 8; k++) {
            uint32_t ad = bbaseB + (uint32_t)((8 + k) * 32);
            asm volatile("ld.shared.b32 %0,[%1];" : "=r"(Bw2[2 * k]) : "r"(ad));
            asm volatile("ld.shared.b32 %0,[%1];" : "=r"(Bw2[2 * k + 1]) : "r"(ad + 16));
        }
#pragma unroll
        for (int k = 0; k < 8; k++) {
            int kt = 8 + k;
            if (k & 1) {
                MMA_BF16(b0o, A[0][kt], Bw2[2 * k], Bw2[2 * k + 1]);
                MMA_BF16(b1o, A[1][kt], Bw2[2 * k], Bw2[2 * k + 1]);
            } else {
                MMA_BF16(b0e, A[0][kt], Bw2[2 * k], Bw2[2 * k + 1]);
                MMA_BF16(b1e, A[1][kt], Bw2[2 * k], Bw2[2 * k + 1]);
            }
        }

        // mid-iteration: reload em for t+1 (arrives well before next use)
        if (t + 1 < TT) {
            const float* qA0 = pA0 + (size_t)(t + 1) * NS;
            const float* qA1 = pA1 + (size_t)(t + 1) * NS;
            const float* qB0 = pB0 + (size_t)(t + 1) * NS;
            const float* qB1 = pB1 + (size_t)(t + 1) * NS;
            em[0] = qA0[m00]; em[1] = qA1[m00]; em[2] = qA0[m01]; em[3] = qA1[m01];
            em[4] = qA0[m10]; em[5] = qA1[m10]; em[6] = qA0[m11]; em[7] = qA1[m11];
            em[8] = qB0[m00]; em[9] = qB1[m00]; em[10] = qB0[m01]; em[11] = qB1[m01];
            em[12] = qB0[m10]; em[13] = qB1[m10]; em[14] = qB0[m11]; em[15] = qB1[m11];
        }

        // rare masked path: per-batch sums of current ea (all 16 rows)
        float Sv0 = 0.f, Sv1 = 0.f, Sv2 = 0.f, Sv3 = 0.f;
        if (mw != 0xFFFFu) {
            float sA = 0.f, sB = 0.f;
#pragma unroll
            for (int q = 0; q < 4; q++) {
                uint32_t v;
                uint32_t ad = bufb + (uint32_t)(wid * RSB + (lane * 4 + q) * 4);
                asm volatile("ld.shared.b32 %0,[%1];" : "=r"(v) : "r"(ad));
                sA += __uint_as_float(v << 16) + __uint_as_float(v & 0xFFFF0000u);
                uint32_t ad2 = ad + 8u * RSB;
                asm volatile("ld.shared.b32 %0,[%1];" : "=r"(v) : "r"(ad2));
                sB += __uint_as_float(v << 16) + __uint_as_float(v & 0xFFFF0000u);
            }
#pragma unroll
            for (int o = 16; o; o >>= 1) {
                sA += __shfl_xor_sync(~0u, sA, o);
                sB += __shfl_xor_sync(~0u, sB, o);
            }
            if (lane == 0) { Ssm[wid] = sA; Ssm[wid + 8] = sB; }
            __syncthreads();
            Sv0 = Ssm[n0] * invM0;
            Sv1 = Ssm[n1] * invM1;
            Sv2 = Ssm[n2] * invM2;
            Sv3 = Ssm[n3] * invM3;
        }

        const uint32_t nxtb = smem_base + SM_EA + (cur ^ 1u) * EABUF;

        // ---- epilogue A ----
        {
            float u00 = (a0e[0] + a0o[0]) * es[0], u01 = (a0e[1] + a0o[1]) * es[1];
            float u02 = (a0e[2] + a0o[2]) * es[2], u03 = (a0e[3] + a0o[3]) * es[3];
            float u10 = (a1e[0] + a1o[0]) * es[4], u11 = (a1e[1] + a1o[1]) * es[5];
            float u12 = (a1e[2] + a1o[2]) * es[6], u13 = (a1e[3] + a1o[3]) * es[7];
            if (mw != 0xFFFFu) {
                if (!((mw >> n0) & 1u)) { u00 = Sv0; u02 = Sv0; u10 = Sv0; u12 = Sv0; }
                if (!((mw >> n1) & 1u)) { u01 = Sv1; u03 = Sv1; u11 = Sv1; u13 = Sv1; }
            }
            uint32_t w0, w1, w2, w3;
            asm volatile("cvt.rn.bf16x2.f32 %0, %1, %2;" : "=r"(w0) : "f"(u02), "f"(u00));
            asm volatile("cvt.rn.bf16x2.f32 %0, %1, %2;" : "=r"(w1) : "f"(u12), "f"(u10));
            asm volatile("cvt.rn.bf16x2.f32 %0, %1, %2;" : "=r"(w2) : "f"(u03), "f"(u01));
            asm volatile("cvt.rn.bf16x2.f32 %0, %1, %2;" : "=r"(w3) : "f"(u13), "f"(u11));
            uint32_t a0 = nxtb + (uint32_t)(n0 * RSB) + stoff;
            uint32_t a1 = nxtb + (uint32_t)(n1 * RSB) + stoff;
            asm volatile("st.shared.v2.b32 [%0], {%1,%2};" :: "r"(a0), "r"(w0), "r"(w1));
            asm volatile("st.shared.v2.b32 [%0], {%1,%2};" :: "r"(a1), "r"(w2), "r"(w3));
            if (tid < 4) {
                mslotF[(cur ^ 1u) * 16 + n0] = u00;
                mslotF[(cur ^ 1u) * 16 + n1] = u01;
            }
        }
        // ---- epilogue B ----
        {
            float u00 = (b0e[0] + b0o[0]) * es[8],  u01 = (b0e[1] + b0o[1]) * es[9];
            float u02 = (b0e[2] + b0o[2]) * es[10], u03 = (b0e[3] + b0o[3]) * es[11];
            float u10 = (b1e[0] + b1o[0]) * es[12], u11 = (b1e[1] + b1o[1]) * es[13];
            float u12 = (b1e[2] + b1o[2]) * es[14], u13 = (b1e[3] + b1o[3]) * es[15];
            if (mw != 0xFFFFu) {
                if (!((mw >> n2) & 1u)) { u00 = Sv2; u02 = Sv2; u10 = Sv2; u12 = Sv2; }
                if (!((mw >> n3) & 1u)) { u01 = Sv3; u03 = Sv3; u11 = Sv3; u13 = Sv3; }
            }
            uint32_t w0, w1, w2, w3;
            asm volatile("cvt.rn.bf16x2.f32 %0, %1, %2;" : "=r"(w0) : "f"(u02), "f"(u00));
            asm volatile("cvt.rn.bf16x2.f32 %0, %1, %2;" : "=r"(w1) : "f"(u12), "f"(u10));
            asm volatile("cvt.rn.bf16x2.f32 %0, %1, %2;" : "=r"(w2) : "f"(u03), "f"(u01));
            asm volatile("cvt.rn.bf16x2.f32 %0, %1, %2;" : "=r"(w3) : "f"(u13), "f"(u11));
            uint32_t a0 = nxtb + (uint32_t)(n2 * RSB) + stoff;
            uint32_t a1 = nxtb + (uint32_t)(n3 * RSB) + stoff;
            asm volatile("st.shared.v2.b32 [%0], {%1,%2};" :: "r"(a0), "r"(w0), "r"(w1));
            asm volatile("st.shared.v2.b32 [%0], {%1,%2};" :: "r"(a1), "r"(w2), "r"(w3));
            if (tid < 4) {
                mslotF[(cur ^ 1u) * 16 + n2] = u00;
                mslotF[(cur ^ 1u) * 16 + n3] = u01;
            }
        }
        __syncthreads();
        cur ^= 1u;
    }

    // epilogue: den[b] = C0 + ksum*ln2 + log(sum ea * exp(trans[STOP,.]))
    {
        int st = permf(tid);
        float ets = __expf(trans[STOP_TAG * NS + st]);
        const uint32_t bufb = smem_base + SM_EA + cur * EABUF;
        float v[NB];
#pragma unroll
        for (int n = 0; n < NB; n++) {
            uint32_t hv;
            uint32_t ad = bufb + (uint32_t)(n * RSB + tid * 2);
            asm volatile("ld.shared.u16 %0,[%1];" : "=r"(hv) : "r"(ad));
            v[n] = __uint_as_float(hv << 16) * ets;
        }
#pragma unroll
        for (int n = 0; n < NB; n++) {
            float s = v[n];
#pragma unroll
            for (int o = 16; o; o >>= 1) s += __shfl_xor_sync(~0u, s, o);
            if (lane == 0) redsm[wid * 16 + n] = s;
        }
        if (tid < 4) {
            kssm[n0] = ksum0; kssm[n1] = ksum1;
            kssm[n2] = ksum2; kssm[n3] = ksum3;
        }
        __syncthreads();
        if (tid < NB) {
            float s = 0.f;
#pragma unroll
            for (int w = 0; w < 8; w++) s += redsm[w * 16 + tid];
            g_den[bb + tid] = C0sm[tid] + (float)kssm[tid] * LN2F + __logf(s);
        }
    }
}

// ---------------------------------------------------------------------------
// Numerator: 1 warp per batch
// ---------------------------------------------------------------------------
__global__ void num_kernel(const float* __restrict__ inputs,
                           const float* __restrict__ trans,
                           const int* __restrict__ tags,
                           const int* __restrict__ mask)
{
    int b = blockIdx.x;
    int lane = threadIdx.x;
    const int* tg = tags + b * TT;
    const int* mk = mask + b * TT;
    float sc = 0.f;
    int mc = 0;
    for (int t = lane; t < TT; t += 32) {
        int tgt = tg[t];
        int m = mk[t];
        mc += m;
        if (t >= 1) sc += trans[tgt * NS + tg[t - 1]] * (float)m;
        if (t < TT - 1) sc += inputs[((size_t)b * TT + t) * NS + tgt] * (float)m;
    }
#pragma unroll
    for (int o = 16; o; o >>= 1) {
        sc += __shfl_xor_sync(0xffffffffu, sc, o);
        mc += __shfl_xor_sync(0xffffffffu, mc, o);
    }
    if (lane == 0) {
        sc += trans[tg[0] * NS + START_TAG];
        int li = mc - 1;
        if (li < 0) li = 0;
        int lt = tg[li];
        sc += trans[STOP_TAG * NS + lt]
            + inputs[((size_t)b * TT + (TT - 1)) * NS + lt] * (float)mk[TT - 1];
        g_num[b] = sc;
    }
}

// ---------------------------------------------------------------------------
// Final reduce: sum_b (num - den)
// ---------------------------------------------------------------------------
__global__ void final_kernel(float* __restrict__ out)
{
    __shared__ float red[8];
    int tid = threadIdx.x;
    int lane = tid & 31, wid = tid >> 5;
    float v = g_num[tid] - g_den[tid];
#pragma unroll
    for (int o = 16; o; o >>= 1) v += __shfl_xor_sync(0xffffffffu, v, o);
    if (lane == 0) red[wid] = v;
    __syncthreads();
    if (tid == 0) {
        float s = 0.f;
#pragma unroll
        for (int w = 0; w < 8; w++) s += red[w];
        out[0] = s;
    }
}

extern "C" void kernel_launch(void* const* d_in, const int* in_sizes, int n_in,
                              void* d_out, int out_size)
{
    const float* inputs = (const float*)d_in[0];
    const float* trans  = (const float*)d_in[1];
    const int*   tags   = (const int*)d_in[2];
    const int*   mask   = (const int*)d_in[3];

    prep_kernel<<<256, 256>>>(trans);
    forward_kernel<<<NCTA, 256>>>(inputs, trans, mask);
    num_kernel<<<BB, 32>>>(inputs, trans, tags, mask);
    final_kernel<<<1, 256>>>((float*)d_out);
}

// round 16
// speedup vs baseline: 1.1947x; 1.0002x over previous
#include <cuda_runtime.h>
#include <cuda_bf16.h>
#include <cstdint>

#define BB 256
#define TT 512
#define NS 256
#define START_TAG 254
#define STOP_TAG 255
#define LN2F 0.6931471805599453f
#define NB 16
#define NCTA (BB / NB)         // 16 CTAs, 2 groups of 8 batches each
#define RSB 528                // ea row stride bytes (132 words -> conflict-free)
#define EABUF (NB * RSB)       // 8448

// scratch (allocation-free rule: __device__ globals)
__device__ float g_den[BB];
__device__ float g_num[BB];
// E = exp(trans) bf16, columns PRE-PERMUTED: g_Ebf[r*256+x] = exp(trans[r][perm(x)])
// perm(x) = 32*(x>>5) + ((x>>2)&7) + 8*(x&3)
__device__ unsigned short g_Ebf[NS * NS];

__device__ __forceinline__ int permf(int x) {
    return 32 * (x >> 5) + ((x >> 2) & 7) + 8 * (x & 3);
}
__device__ __forceinline__ int iperm(int s) {
    return 32 * (s >> 5) + 4 * (s & 7) + ((s >> 3) & 3);
}

// ---------------------------------------------------------------------------
// smem layout (static, ~19.3 KB)
// ---------------------------------------------------------------------------
#define SM_EA    0        // 2 x 8448 ea double buffer: [n][x] bf16 (16 rows)
#define SM_MASK  16896    // 512 u32 mask bitfields (16 bits each)
#define SM_MSLOT 18944    // 2 x 16 floats (state-0 value per batch, renorm probe)
#define SM_C0    19072    // 16 floats
#define SM_RED   19136    // 128 floats (8 warps x 16)
#define SM_KS    19648    // 16 ints
#define SM_SS    19712    // 16 floats
#define SM_TOTAL 19776

#define MMA_BF16(d, a, b0, b1) \
    asm volatile( \
        "mma.sync.aligned.m16n8k16.row.col.f32.bf16.bf16.f32 " \
        "{%0,%1,%2,%3},{%4,%5,%6,%7},{%8,%9},{%0,%1,%2,%3};" \
        : "+f"((d)[0]), "+f"((d)[1]), "+f"((d)[2]), "+f"((d)[3]) \
        : "r"((a)[0]), "r"((a)[1]), "r"((a)[2]), "r"((a)[3]), "r"(b0), "r"(b1))

// ---------------------------------------------------------------------------
// Prep: permuted bf16 E
// ---------------------------------------------------------------------------
__global__ void prep_kernel(const float* __restrict__ trans) {
    int gid = blockIdx.x * blockDim.x + threadIdx.x;  // 0..65535
    int r = gid >> 8, x = gid & 255;
    g_Ebf[gid] = __bfloat16_as_ushort(__float2bfloat16(__expf(trans[r * NS + permf(x)])));
}

// ---------------------------------------------------------------------------
// Forward recursion via mma.sync bf16: TWO 8-batch groups per CTA sharing the
// register-resident A fragments; one barrier per double-step.
// ---------------------------------------------------------------------------
__global__ void __launch_bounds__(256, 1) forward_kernel(
    const float* __restrict__ inputs,
    const float* __restrict__ trans,
    const int* __restrict__ mask)
{
    __shared__ __align__(16) char smem[SM_TOTAL];
    const uint32_t smem_base = (uint32_t)__cvta_generic_to_shared(smem);
    float*    mslotF = (float*)(smem + SM_MSLOT);
    uint32_t* masksS = (uint32_t*)(smem + SM_MASK);
    float*    C0sm   = (float*)(smem + SM_C0);
    float*    redsm  = (float*)(smem + SM_RED);
    int*      kssm   = (int*)(smem + SM_KS);
    float*    Ssm    = (float*)(smem + SM_SS);

    const int tid  = threadIdx.x;
    const int lane = tid & 31;
    const int wid  = tid >> 5;
    const int gidr = lane >> 2;   // groupID
    const int tig  = lane & 3;    // thread-in-group
    const int wbase = wid * 32;   // warp's state base
    const int bb    = blockIdx.x * NB;
    const int n0 = 2 * tig, n1 = n0 + 1;          // group A batch rows
    const int n2 = n0 + 8, n3 = n1 + 8;           // group B batch rows

    // mask bitfields (16 bits)
    for (int tt = tid; tt < TT; tt += 256) {
        uint32_t w = 0;
#pragma unroll
        for (int n = 0; n < NB; n++) w |= (mask[(bb + n) * TT + tt] ? 1u : 0u) << n;
        masksS[tt] = w;
    }

    // A fragments from permuted E (128 u32/thread, shared by both groups)
    uint32_t A[2][16][4];
    {
#pragma unroll
        for (int mt = 0; mt < 2; mt++) {
            int r0 = wbase + mt * 16 + gidr, r1 = r0 + 8;
#pragma unroll
            for (int kt = 0; kt < 16; kt++) {
                int c0 = kt * 16 + tig * 2;
                A[mt][kt][0] = *(const uint32_t*)&g_Ebf[r0 * NS + c0];
                A[mt][kt][1] = *(const uint32_t*)&g_Ebf[r1 * NS + c0];
                A[mt][kt][2] = *(const uint32_t*)&g_Ebf[r0 * NS + c0 + 8];
                A[mt][kt][3] = *(const uint32_t*)&g_Ebf[r1 * NS + c0 + 8];
            }
        }
    }

    // alpha0: per-batch max -> C0; ea0 at physical iperm(state)
    {
        float a0v[NB];
        float tS = trans[tid * NS + START_TAG];
#pragma unroll
        for (int n = 0; n < NB; n++)
            a0v[n] = tS + inputs[((size_t)(bb + n) * TT) * NS + tid];
#pragma unroll
        for (int n = 0; n < NB; n++) {
            float m = a0v[n];
#pragma unroll
            for (int o = 16; o; o >>= 1) m = fmaxf(m, __shfl_xor_sync(~0u, m, o));
            if (lane == 0) redsm[wid * 16 + n] = m;
        }
        __syncthreads();
        if (tid < NB) {
            float m = -INFINITY;
#pragma unroll
            for (int w = 0; w < 8; w++) m = fmaxf(m, redsm[w * 16 + tid]);
            C0sm[tid] = m;
        }
        __syncthreads();
        int xph = iperm(tid);
#pragma unroll
        for (int n = 0; n < NB; n++) {
            float e = __expf(a0v[n] - C0sm[n]);
            unsigned short h = __bfloat16_as_ushort(__float2bfloat16(e));
            uint32_t ad = smem_base + SM_EA + (uint32_t)(n * RSB + xph * 2);
            asm volatile("st.shared.b16 [%0], %1;" :: "r"(ad), "h"(h));
            if (tid == 0) mslotF[n] = e;
        }
        __syncthreads();
    }

    // emission pointers (4 logical states x 4 batch rows)
    const float* pA0 = inputs + (size_t)(bb + n0) * TT * NS;
    const float* pA1 = inputs + (size_t)(bb + n1) * TT * NS;
    const float* pB0 = inputs + (size_t)(bb + n2) * TT * NS;
    const float* pB1 = inputs + (size_t)(bb + n3) * TT * NS;
    const int m00 = wbase + gidr, m01 = m00 + 8, m10 = m00 + 16, m11 = m00 + 24;

    float em[16];
    {
        const float* qA0 = pA0 + (size_t)1 * NS;
        const float* qA1 = pA1 + (size_t)1 * NS;
        const float* qB0 = pB0 + (size_t)1 * NS;
        const float* qB1 = pB1 + (size_t)1 * NS;
        em[0] = qA0[m00]; em[1] = qA1[m00]; em[2] = qA0[m01]; em[3] = qA1[m01];
        em[4] = qA0[m10]; em[5] = qA1[m10]; em[6] = qA0[m11]; em[7] = qA1[m11];
        em[8] = qB0[m00]; em[9] = qB1[m00]; em[10] = qB0[m01]; em[11] = qB1[m01];
        em[12] = qB0[m10]; em[13] = qB1[m10]; em[14] = qB0[m11]; em[15] = qB1[m11];
    }

    int ksum0 = 0, ksum1 = 0, ksum2 = 0, ksum3 = 0;
    uint32_t cur = 0;
    const uint32_t stoff = (uint32_t)((wbase + 4 * gidr) * 2);

    for (int t = 1; t < TT; t++) {
        const uint32_t bufb = smem_base + SM_EA + cur * EABUF;
        const uint32_t bbaseA = bufb + (uint32_t)(gidr * RSB + tig * 4);
        const uint32_t bbaseB = bbaseA + 8u * RSB;

        // ---- group A first-half B-loads (pairs at kt*32 and kt*32+16) ----
        uint32_t Bw[16];
#pragma unroll
        for (int k = 0; k < 8; k++) {
            uint32_t ad = bbaseA + (uint32_t)(k * 32);
            asm volatile("ld.shared.b32 %0,[%1];" : "=r"(Bw[2 * k]) : "r"(ad));
            asm volatile("ld.shared.b32 %0,[%1];" : "=r"(Bw[2 * k + 1]) : "r"(ad + 16));
        }

        // ---- hoisted scalars: renorm (stale state-0), mask, es = exp(em)*invM
        float ms0 = mslotF[cur * 16 + n0];
        float ms1 = mslotF[cur * 16 + n1];
        float ms2 = mslotF[cur * 16 + n2];
        float ms3 = mslotF[cur * 16 + n3];
        uint32_t mw = masksS[t - 1];
        uint32_t e0b = (__float_as_uint(ms0) >> 23) & 0xFFu;
        uint32_t e1b = (__float_as_uint(ms1) >> 23) & 0xFFu;
        uint32_t e2b = (__float_as_uint(ms2) >> 23) & 0xFFu;
        uint32_t e3b = (__float_as_uint(ms3) >> 23) & 0xFFu;
        ksum0 += (int)e0b - 127;
        ksum1 += (int)e1b - 127;
        ksum2 += (int)e2b - 127;
        ksum3 += (int)e3b - 127;
        float invM0 = __uint_as_float((254u - e0b) << 23);
        float invM1 = __uint_as_float((254u - e1b) << 23);
        float invM2 = __uint_as_float((254u - e2b) << 23);
        float invM3 = __uint_as_float((254u - e3b) << 23);
        float es[16];
#pragma unroll
        for (int i = 0; i < 8; i += 2) {
            es[i]     = __expf(em[i]) * invM0;
            es[i + 1] = __expf(em[i + 1]) * invM1;
            es[8 + i]     = __expf(em[8 + i]) * invM2;
            es[8 + i + 1] = __expf(em[8 + i + 1]) * invM3;
        }

        // ---- group A MMA: 32 HMMA in 4 chains ----
        float a0e[4] = {0.f, 0.f, 0.f, 0.f}, a0o[4] = {0.f, 0.f, 0.f, 0.f};
        float a1e[4] = {0.f, 0.f, 0.f, 0.f}, a1o[4] = {0.f, 0.f, 0.f, 0.f};
#pragma unroll
        for (int k = 0; k < 8; k++) {
            if (k & 1) {
                MMA_BF16(a0o, A[0][k], Bw[2 * k], Bw[2 * k + 1]);
                MMA_BF16(a1o, A[1][k], Bw[2 * k], Bw[2 * k + 1]);
            } else {
                MMA_BF16(a0e, A[0][k], Bw[2 * k], Bw[2 * k + 1]);
                MMA_BF16(a1e, A[1][k], Bw[2 * k], Bw[2 * k + 1]);
            }
        }
        uint32_t Bw2[16];
#pragma unroll
        for (int k = 0; k < 8; k++) {
            uint32_t ad = bbaseA + (uint32_t)((8 + k) * 32);
            asm volatile("ld.shared.b32 %0,[%1];" : "=r"(Bw2[2 * k]) : "r"(ad));
            asm volatile("ld.shared.b32 %0,[%1];" : "=r"(Bw2[2 * k + 1]) : "r"(ad + 16));
        }
#pragma unroll
        for (int k = 0; k < 8; k++) {
            int kt = 8 + k;
            if (k & 1) {
                MMA_BF16(a0o, A[0][kt], Bw2[2 * k], Bw2[2 * k + 1]);
                MMA_BF16(a1o, A[1][kt], Bw2[2 * k], Bw2[2 * k + 1]);
            } else {
                MMA_BF16(a0e, A[0][kt], Bw2[2 * k], Bw2[2 * k + 1]);
                MMA_BF16(a1e, A[1][kt], Bw2[2 * k], Bw2[2 * k + 1]);
            }
        }

        // ---- group B loads + MMA (hides A's D latency) ----
        float b0e[4] = {0.f, 0.f, 0.f, 0.f}, b0o[4] = {0.f, 0.f, 0.f, 0.f};
        float b1e[4] = {0.f, 0.f, 0.f, 0.f}, b1o[4] = {0.f, 0.f, 0.f, 0.f};
#pragma unroll
        for (int k = 0; k < 8; k++) {
            uint32_t ad = bbaseB + (uint32_t)(k * 32);
            asm volatile("ld.shared.b32 %0,[%1];" : "=r"(Bw[2 * k]) : "r"(ad));
            asm volatile("ld.shared.b32 %0,[%1];" : "=r"(Bw[2 * k + 1]) : "r"(ad + 16));
        }
#pragma unroll
        for (int k = 0; k < 8; k++) {
            if (k & 1) {
                MMA_BF16(b0o, A[0][k], Bw[2 * k], Bw[2 * k + 1]);
                MMA_BF16(b1o, A[1][k], Bw[2 * k], Bw[2 * k + 1]);
            } else {
                MMA_BF16(b0e, A[0][k], Bw[2 * k], Bw[2 * k + 1]);
                MMA_BF16(b1e, A[1][k], Bw[2 * k], Bw[2 * k + 1]);
            }
        }
#pragma unroll
        for (int k = 0; k < 8; k++) {
            uint32_t ad = bbaseB + (uint32_t)((8 + k) * 32);
            asm volatile("ld.shared.b32 %0,[%1];" : "=r"(Bw2[2 * k]) : "r"(ad));
            asm volatile("ld.shared.b32 %0,[%1];" : "=r"(Bw2[2 * k + 1]) : "r"(ad + 16));
        }
#pragma unroll
        for (int k = 0; k < 8; k++) {
            int kt = 8 + k;
            if (k & 1) {
                MMA_BF16(b0o, A[0][kt], Bw2[2 * k], Bw2[2 * k + 1]);
                MMA_BF16(b1o, A[1][kt], Bw2[2 * k], Bw2[2 * k + 1]);
            } else {
                MMA_BF16(b0e, A[0][kt], Bw2[2 * k], Bw2[2 * k + 1]);
                MMA_BF16(b1e, A[1][kt], Bw2[2 * k], Bw2[2 * k + 1]);
            }
        }

        // mid-iteration: reload em for t+1 (arrives well before next use)
        if (t + 1 < TT) {
            const float* qA0 = pA0 + (size_t)(t + 1) * NS;
            const float* qA1 = pA1 + (size_t)(t + 1) * NS;
            const float* qB0 = pB0 + (size_t)(t + 1) * NS;
            const float* qB1 = pB1 + (size_t)(t + 1) * NS;
            em[0] = qA0[m00]; em[1] = qA1[m00]; em[2] = qA0[m01]; em[3] = qA1[m01];
            em[4] = qA0[m10]; em[5] = qA1[m10]; em[6] = qA0[m11]; em[7] = qA1[m11];
            em[8] = qB0[m00]; em[9] = qB1[m00]; em[10] = qB0[m01]; em[11] = qB1[m01];
            em[12] = qB0[m10]; em[13] = qB1[m10]; em[14] = qB0[m11]; em[15] = qB1[m11];
        }

        // rare masked path: per-batch sums of current ea (all 16 rows)
        float Sv0 = 0.f, Sv1 = 0.f, Sv2 = 0.f, Sv3 = 0.f;
        if (mw != 0xFFFFu) {
            float sA = 0.f, sB = 0.f;
#pragma unroll
            for (int q = 0; q < 4; q++) {
                uint32_t v;
                uint32_t ad = bufb + (uint32_t)(wid * RSB + (lane * 4 + q) * 4);
                asm volatile("ld.shared.b32 %0,[%1];" : "=r"(v) : "r"(ad));
                sA += __uint_as_float(v << 16) + __uint_as_float(v & 0xFFFF0000u);
                uint32_t ad2 = ad + 8u * RSB;
                asm volatile("ld.shared.b32 %0,[%1];" : "=r"(v) : "r"(ad2));
                sB += __uint_as_float(v << 16) + __uint_as_float(v & 0xFFFF0000u);
            }
#pragma unroll
            for (int o = 16; o; o >>= 1) {
                sA += __shfl_xor_sync(~0u, sA, o);
                sB += __shfl_xor_sync(~0u, sB, o);
            }
            if (lane == 0) { Ssm[wid] = sA; Ssm[wid + 8] = sB; }
            __syncthreads();
            Sv0 = Ssm[n0] * invM0;
            Sv1 = Ssm[n1] * invM1;
            Sv2 = Ssm[n2] * invM2;
            Sv3 = Ssm[n3] * invM3;
        }

        const uint32_t nxtb = smem_base + SM_EA + (cur ^ 1u) * EABUF;

        // ---- epilogue A ----
        {
            float u00 = (a0e[0] + a0o[0]) * es[0], u01 = (a0e[1] + a0o[1]) * es[1];
            float u02 = (a0e[2] + a0o[2]) * es[2], u03 = (a0e[3] + a0o[3]) * es[3];
            float u10 = (a1e[0] + a1o[0]) * es[4], u11 = (a1e[1] + a1o[1]) * es[5];
            float u12 = (a1e[2] + a1o[2]) * es[6], u13 = (a1e[3] + a1o[3]) * es[7];
            if (mw != 0xFFFFu) {
                if (!((mw >> n0) & 1u)) { u00 = Sv0; u02 = Sv0; u10 = Sv0; u12 = Sv0; }
                if (!((mw >> n1) & 1u)) { u01 = Sv1; u03 = Sv1; u11 = Sv1; u13 = Sv1; }
            }
            uint32_t w0, w1, w2, w3;
            asm volatile("cvt.rn.bf16x2.f32 %0, %1, %2;" : "=r"(w0) : "f"(u02), "f"(u00));
            asm volatile("cvt.rn.bf16x2.f32 %0, %1, %2;" : "=r"(w1) : "f"(u12), "f"(u10));
            asm volatile("cvt.rn.bf16x2.f32 %0, %1, %2;" : "=r"(w2) : "f"(u03), "f"(u01));
            asm volatile("cvt.rn.bf16x2.f32 %0, %1, %2;" : "=r"(w3) : "f"(u13), "f"(u11));
            uint32_t a0 = nxtb + (uint32_t)(n0 * RSB) + stoff;
            uint32_t a1 = nxtb + (uint32_t)(n1 * RSB) + stoff;
            asm volatile("st.shared.v2.b32 [%0], {%1,%2};" :: "r"(a0), "r"(w0), "r"(w1));
            asm volatile("st.shared.v2.b32 [%0], {%1,%2};" :: "r"(a1), "r"(w2), "r"(w3));
            if (tid < 4) {
                mslotF[(cur ^ 1u) * 16 + n0] = u00;
                mslotF[(cur ^ 1u) * 16 + n1] = u01;
            }
        }
        // ---- epilogue B ----
        {
            float u00 = (b0e[0] + b0o[0]) * es[8],  u01 = (b0e[1] + b0o[1]) * es[9];
            float u02 = (b0e[2] + b0o[2]) * es[10], u03 = (b0e[3] + b0o[3]) * es[11];
            float u10 = (b1e[0] + b1o[0]) * es[12], u11 = (b1e[1] + b1o[1]) * es[13];
            float u12 = (b1e[2] + b1o[2]) * es[14], u13 = (b1e[3] + b1o[3]) * es[15];
            if (mw != 0xFFFFu) {
                if (!((mw >> n2) & 1u)) { u00 = Sv2; u02 = Sv2; u10 = Sv2; u12 = Sv2; }
                if (!((mw >> n3) & 1u)) { u01 = Sv3; u03 = Sv3; u11 = Sv3; u13 = Sv3; }
            }
            uint32_t w0, w1, w2, w3;
            asm volatile("cvt.rn.bf16x2.f32 %0, %1, %2;" : "=r"(w0) : "f"(u02), "f"(u00));
            asm volatile("cvt.rn.bf16x2.f32 %0, %1, %2;" : "=r"(w1) : "f"(u12), "f"(u10));
            asm volatile("cvt.rn.bf16x2.f32 %0, %1, %2;" : "=r"(w2) : "f"(u03), "f"(u01));
            asm volatile("cvt.rn.bf16x2.f32 %0, %1, %2;" : "=r"(w3) : "f"(u13), "f"(u11));
            uint32_t a0 = nxtb + (uint32_t)(n2 * RSB) + stoff;
            uint32_t a1 = nxtb + (uint32_t)(n3 * RSB) + stoff;
            asm volatile("st.shared.v2.b32 [%0], {%1,%2};" :: "r"(a0), "r"(w0), "r"(w1));
            asm volatile("st.shared.v2.b32 [%0], {%1,%2};" :: "r"(a1), "r"(w2), "r"(w3));
            if (tid < 4) {
                mslotF[(cur ^ 1u) * 16 + n2] = u00;
                mslotF[(cur ^ 1u) * 16 + n3] = u01;
            }
        }
        __syncthreads();
        cur ^= 1u;
    }

    // epilogue: den[b] = C0 + ksum*ln2 + log(sum ea * exp(trans[STOP,.]))
    {
        int st = permf(tid);
        float ets = __expf(trans[STOP_TAG * NS + st]);
        const uint32_t bufb = smem_base + SM_EA + cur * EABUF;
        float v[NB];
#pragma unroll
        for (int n = 0; n < NB; n++) {
            uint32_t hv;
            uint32_t ad = bufb + (uint32_t)(n * RSB + tid * 2);
            asm volatile("ld.shared.u16 %0,[%1];" : "=r"(hv) : "r"(ad));
            v[n] = __uint_as_float(hv << 16) * ets;
        }
#pragma unroll
        for (int n = 0; n < NB; n++) {
            float s = v[n];
#pragma unroll
            for (int o = 16; o; o >>= 1) s += __shfl_xor_sync(~0u, s, o);
            if (lane == 0) redsm[wid * 16 + n] = s;
        }
        if (tid < 4) {
            kssm[n0] = ksum0; kssm[n1] = ksum1;
            kssm[n2] = ksum2; kssm[n3] = ksum3;
        }
        __syncthreads();
        if (tid < NB) {
            float s = 0.f;
#pragma unroll
            for (int w = 0; w < 8; w++) s += redsm[w * 16 + tid];
            g_den[bb + tid] = C0sm[tid] + (float)kssm[tid] * LN2F + __logf(s);
        }
    }
}

// ---------------------------------------------------------------------------
// Numerator: 1 warp per batch
// ---------------------------------------------------------------------------
__global__ void num_kernel(const float* __restrict__ inputs,
                           const float* __restrict__ trans,
                           const int* __restrict__ tags,
                           const int* __restrict__ mask)
{
    int b = blockIdx.x;
    int lane = threadIdx.x;
    const int* tg = tags + b * TT;
    const int* mk = mask + b * TT;
    float sc = 0.f;
    int mc = 0;
    for (int t = lane; t < TT; t += 32) {
        int tgt = tg[t];
        int m = mk[t];
        mc += m;
        if (t >= 1) sc += trans[tgt * NS + tg[t - 1]] * (float)m;
        if (t < TT - 1) sc += inputs[((size_t)b * TT + t) * NS + tgt] * (float)m;
    }
#pragma unroll
    for (int o = 16; o; o >>= 1) {
        sc += __shfl_xor_sync(0xffffffffu, sc, o);
        mc += __shfl_xor_sync(0xffffffffu, mc, o);
    }
    if (lane == 0) {
        sc += trans[tg[0] * NS + START_TAG];
        int li = mc - 1;
        if (li < 0) li = 0;
        int lt = tg[li];
        sc += trans[STOP_TAG * NS + lt]
            + inputs[((size_t)b * TT + (TT - 1)) * NS + lt] * (float)mk[TT - 1];
        g_num[b] = sc;
    }
}

// ---------------------------------------------------------------------------
// Final reduce: sum_b (num - den)
// ---------------------------------------------------------------------------
__global__ void final_kernel(float* __restrict__ out)
{
    __shared__ float red[8];
    int tid = threadIdx.x;
    int lane = tid & 31, wid = tid >> 5;
    float v = g_num[tid] - g_den[tid];
#pragma unroll
    for (int o = 16; o; o >>= 1) v += __shfl_xor_sync(0xffffffffu, v, o);
    if (lane == 0) red[wid] = v;
    __syncthreads();
    if (tid == 0) {
        float s = 0.f;
#pragma unroll
        for (int w = 0; w < 8; w++) s += red[w];
        out[0] = s;
    }
}

extern "C" void kernel_launch(void* const* d_in, const int* in_sizes, int n_in,
                              void* d_out, int out_size)
{
    const float* inputs = (const float*)d_in[0];
    const float* trans  = (const float*)d_in[1];
    const int*   tags   = (const int*)d_in[2];
    const int*   mask   = (const int*)d_in[3];

    prep_kernel<<<256, 256>>>(trans);
    forward_kernel<<<NCTA, 256>>>(inputs, trans, mask);
    num_kernel<<<BB, 32>>>(inputs, trans, tags, mask);
    final_kernel<<<1, 256>>>((float*)d_out);
}